// round 15
// baseline (speedup 1.0000x reference)
#include <cuda_runtime.h>
#include <cuda_fp16.h>
#include <cstdint>
#include <math.h>

static constexpr int TOK  = 8192;
static constexpr int HID  = 7168;
static constexpr int NEXP = 256;
static constexpr int BM = 128, BN = 64, BK = 32;
static constexpr int KCH = HID / BK;                // 224
static constexpr int A_ARR_B = 128 * 80;            // 10240 bytes (128 rows x 80B)
static constexpr int B_ARR_B = 64 * 80;             // 5120 bytes  (64 rows x 80B)
static constexpr int STAGE_B = 2 * A_ARR_B + 2 * B_ARR_B;  // Ah, Al, Bh, Bl = 30720
static constexpr int OFF_BH  = 2 * A_ARR_B;         // 20480
static constexpr int OFF_BL  = 2 * A_ARR_B + B_ARR_B; // 25600
static constexpr int SMEM_TOTAL = 2 * STAGE_B;      // 61440 bytes
static constexpr int MAXFLAG = 256;
static constexpr float WSCALE = 4096.0f;            // keep wl out of fp16 subnormals
static constexpr float TAU   = 3e-6f;               // expert-margin flag threshold (score space)
static constexpr float TAU_G = 6e-6f;               // group-margin flag threshold

__device__ float g_logits[(size_t)TOK * NEXP];
__device__ int   g_flag_cnt;
__device__ int   g_flag_tok[MAXFLAG];
__device__ float g_fix_logit[(size_t)MAXFLAG * NEXP];

// ---------------- helpers ----------------
__device__ __forceinline__ uint32_t smem_u32(const void* p) {
    uint32_t a;
    asm("{ .reg .u64 t; cvta.to.shared.u64 t, %1; cvt.u32.u64 %0, t; }" : "=r"(a) : "l"(p));
    return a;
}
__device__ __forceinline__ void ldsm4(uint32_t* r, uint32_t addr) {
    asm volatile("ldmatrix.sync.aligned.m8n8.x4.shared.b16 {%0,%1,%2,%3}, [%4];"
                 : "=r"(r[0]), "=r"(r[1]), "=r"(r[2]), "=r"(r[3]) : "r"(addr));
}
__device__ __forceinline__ void ldsm2(uint32_t* r, uint32_t addr) {
    asm volatile("ldmatrix.sync.aligned.m8n8.x2.shared.b16 {%0,%1}, [%2];"
                 : "=r"(r[0]), "=r"(r[1]) : "r"(addr));
}
__device__ __forceinline__ void mma16816(float* c, const uint32_t* a, const uint32_t* b) {
    asm volatile("mma.sync.aligned.m16n8k16.row.col.f32.f16.f16.f32 "
                 "{%0,%1,%2,%3}, {%4,%5,%6,%7}, {%8,%9}, {%0,%1,%2,%3};"
                 : "+f"(c[0]), "+f"(c[1]), "+f"(c[2]), "+f"(c[3])
                 : "r"(a[0]), "r"(a[1]), "r"(a[2]), "r"(a[3]), "r"(b[0]), "r"(b[1]));
}
__device__ __forceinline__ uint32_t pack2(half a, half b) {
    __half2 h = __halves2half2(a, b);
    return *reinterpret_cast<uint32_t*>(&h);
}
// split (v*scale) -> hi(4 halves) + lo(4 halves)
__device__ __forceinline__ void split_store(float4 v, float scale, half* ph, half* pl) {
    float vx = v.x * scale, vy = v.y * scale, vz = v.z * scale, vw = v.w * scale;
    half hx = __float2half_rn(vx), hy = __float2half_rn(vy);
    half hz = __float2half_rn(vz), hw = __float2half_rn(vw);
    half lx = __float2half_rn(vx - __half2float(hx));
    half ly = __float2half_rn(vy - __half2float(hy));
    half lz = __float2half_rn(vz - __half2float(hz));
    half lw = __float2half_rn(vw - __half2float(hw));
    uint2 H, L;
    H.x = pack2(hx, hy); H.y = pack2(hz, hw);
    L.x = pack2(lx, ly); L.y = pack2(lz, lw);
    *reinterpret_cast<uint2*>(ph) = H;
    *reinterpret_cast<uint2*>(pl) = L;
}
// monotone u32 key for float compare (handles negatives)
__device__ __forceinline__ uint32_t key_f(float f) {
    uint32_t u = __float_as_uint(f);
    return (u & 0x80000000u) ? ~u : (u | 0x80000000u);
}
__device__ __forceinline__ float unkey_f(uint32_t k) {
    return __uint_as_float((k & 0x80000000u) ? (k ^ 0x80000000u) : ~k);
}

// ---------------- GEMM: logits = X @ W^T (fp16 2-term split, 3x mma.sync) ----------------
// BM=128 x BN=64 tiles, 2 CTAs/SM co-resident to overlap barrier/load stalls.
__global__ void __launch_bounds__(256, 2)
gemm_kernel(const float* __restrict__ X, const float* __restrict__ W) {
    extern __shared__ half sm[];
    const int tid = threadIdx.x;
    const int lid = tid & 31, wid = tid >> 5;
    const int warp_m = wid >> 2;          // 0..1  (64 rows each)
    const int warp_n = wid & 3;           // 0..3  (16 cols each)
    const int m0 = blockIdx.y * BM;
    const int n0 = blockIdx.x * BN;
    const uint32_t sb = smem_u32(sm);

    // reset flag counter for the router (runs strictly after this kernel)
    if (blockIdx.x == 0 && blockIdx.y == 0 && tid == 0) g_flag_cnt = 0;

    const float* Abase = X + (size_t)m0 * HID;
    const float* Bbase = W + (size_t)n0 * HID;

    const int aRow = warp_m * 64 + ((lid >> 3) & 1) * 8 + (lid & 7);
    const int aK   = (lid >> 4) * 8;
    const int bRow = warp_n * 16 + (lid & 7);
    const int bK   = ((lid >> 3) & 1) * 8;

    float acc[4][2][4];
#pragma unroll
    for (int i = 0; i < 4; i++)
#pragma unroll
        for (int j = 0; j < 2; j++)
#pragma unroll
            for (int k = 0; k < 4; k++) acc[i][j][k] = 0.f;

    float4 stg[6];   // 4 A + 2 B

    // prologue: chunk 0
#pragma unroll
    for (int i = 0; i < 4; i++) {
        int idx = tid + 256 * i;
        stg[i] = *reinterpret_cast<const float4*>(Abase + (size_t)(idx >> 3) * HID + (idx & 7) * 4);
    }
#pragma unroll
    for (int i = 0; i < 2; i++) {
        int idx = tid + 256 * i;
        stg[4 + i] = *reinterpret_cast<const float4*>(Bbase + (size_t)(idx >> 3) * HID + (idx & 7) * 4);
    }
    {
        char* s0 = reinterpret_cast<char*>(sm);
#pragma unroll
        for (int i = 0; i < 4; i++) {
            int idx = tid + 256 * i;
            int pos = (idx >> 3) * 80 + (idx & 7) * 8;
            split_store(stg[i], 1.0f, reinterpret_cast<half*>(s0 + pos),
                                      reinterpret_cast<half*>(s0 + A_ARR_B + pos));
        }
#pragma unroll
        for (int i = 0; i < 2; i++) {
            int idx = tid + 256 * i;
            int pos = (idx >> 3) * 80 + (idx & 7) * 8;
            split_store(stg[4 + i], WSCALE, reinterpret_cast<half*>(s0 + OFF_BH + pos),
                                            reinterpret_cast<half*>(s0 + OFF_BL + pos));
        }
    }
    __syncthreads();

    for (int c = 0; c < KCH; c++) {
        const int buf = c & 1;
        if (c + 1 < KCH) {
            const int k0 = (c + 1) * BK;
#pragma unroll
            for (int i = 0; i < 4; i++) {
                int idx = tid + 256 * i;
                stg[i] = *reinterpret_cast<const float4*>(Abase + (size_t)(idx >> 3) * HID + k0 + (idx & 7) * 4);
            }
#pragma unroll
            for (int i = 0; i < 2; i++) {
                int idx = tid + 256 * i;
                stg[4 + i] = *reinterpret_cast<const float4*>(Bbase + (size_t)(idx >> 3) * HID + k0 + (idx & 7) * 4);
            }
        }

        const uint32_t base = sb + buf * STAGE_B;
#pragma unroll
        for (int ks = 0; ks < 2; ks++) {
            uint32_t ah[4][4], al[4][4], bh[2][2], bl[2][2];
#pragma unroll
            for (int mt = 0; mt < 4; mt++) {
                uint32_t ra = base + (uint32_t)((aRow + mt * 16) * 80 + (aK + ks * 16) * 2);
                ldsm4(ah[mt], ra);
                ldsm4(al[mt], ra + A_ARR_B);
            }
#pragma unroll
            for (int nt = 0; nt < 2; nt++) {
                uint32_t rb = base + OFF_BH + (uint32_t)((bRow + nt * 8) * 80 + (bK + ks * 16) * 2);
                ldsm2(bh[nt], rb);
                ldsm2(bl[nt], rb + B_ARR_B);
            }
#pragma unroll
            for (int mt = 0; mt < 4; mt++)
#pragma unroll
                for (int nt = 0; nt < 2; nt++) {
                    mma16816(acc[mt][nt], ah[mt], bh[nt]);
                    mma16816(acc[mt][nt], ah[mt], bl[nt]);
                    mma16816(acc[mt][nt], al[mt], bh[nt]);
                }
        }

        if (c + 1 < KCH) {
            char* sn = reinterpret_cast<char*>(sm) + (buf ^ 1) * STAGE_B;
#pragma unroll
            for (int i = 0; i < 4; i++) {
                int idx = tid + 256 * i;
                int pos = (idx >> 3) * 80 + (idx & 7) * 8;
                split_store(stg[i], 1.0f, reinterpret_cast<half*>(sn + pos),
                                          reinterpret_cast<half*>(sn + A_ARR_B + pos));
            }
#pragma unroll
            for (int i = 0; i < 2; i++) {
                int idx = tid + 256 * i;
                int pos = (idx >> 3) * 80 + (idx & 7) * 8;
                split_store(stg[4 + i], WSCALE, reinterpret_cast<half*>(sn + OFF_BH + pos),
                                                reinterpret_cast<half*>(sn + OFF_BL + pos));
            }
        }
        __syncthreads();
    }

    const float inv = 1.0f / WSCALE;
#pragma unroll
    for (int mt = 0; mt < 4; mt++) {
        int row = m0 + warp_m * 64 + mt * 16 + (lid >> 2);
#pragma unroll
        for (int nt = 0; nt < 2; nt++) {
            int col = n0 + warp_n * 16 + nt * 8 + (lid & 3) * 2;
            *reinterpret_cast<float2*>(g_logits + (size_t)row * NEXP + col) =
                make_float2(acc[mt][nt][0] * inv, acc[mt][nt][1] * inv);
            *reinterpret_cast<float2*>(g_logits + (size_t)(row + 8) * NEXP + col) =
                make_float2(acc[mt][nt][2] * inv, acc[mt][nt][3] * inv);
        }
    }
}

// ---------------- routing decision (one warp per token, REDUX-based) ----------------
template<bool CLEANUP>
__device__ __forceinline__ void route_token(const float* __restrict__ lrow,
                                            const float* __restrict__ bias,
                                            float* __restrict__ out,
                                            int t, int lid, int write_w) {
    float sg[8];
    uint32_t sck[8];          // monotone keys of sc = s + bias
#pragma unroll
    for (int g = 0; g < 8; g++) {
        int e = g * 32 + lid;
        float x = lrow[e];
        float s;
        if (CLEANUP) s = (float)(1.0 / (1.0 + exp(-(double)x)));
        else         s = 1.0f / (1.0f + expf(-x));
        sg[g] = s;
        sck[g] = key_f(s + bias[e]);
    }

    // per-group top-2 sum via redux
    float gs[8];
#pragma unroll
    for (int g = 0; g < 8; g++) {
        uint32_t k = sck[g];
        uint32_t m1 = __reduce_max_sync(0xffffffffu, k);
        unsigned bal = __ballot_sync(0xffffffffu, k == m1);
        int low = __ffs(bal) - 1;
        uint32_t kk = (lid == low) ? 0u : k;
        uint32_t m2 = __reduce_max_sync(0xffffffffu, kk);
        gs[g] = unkey_f(m1) + unkey_f(m2);
    }

    // top-4 groups (lane-local, identical on all lanes; ties -> lowest g)
    unsigned gmask = 0;
    bool fl = false;
    {
        float tmp[8];
#pragma unroll
        for (int g = 0; g < 8; g++) tmp[g] = gs[g];
        float g4 = 0.f, g5 = 0.f;
#pragma unroll
        for (int it = 0; it < 5; it++) {
            float best = -INFINITY; int bi = 0;
#pragma unroll
            for (int g = 0; g < 8; g++) if (tmp[g] > best) { best = tmp[g]; bi = g; }
            if (it < 4) gmask |= 1u << bi;
            if (it == 3) g4 = best;
            if (it == 4) g5 = best;
#pragma unroll
            for (int g = 0; g < 8; g++) if (g == bi) tmp[g] = -INFINITY;
        }
        fl = (g4 - g5 < TAU_G);
    }

    uint32_t mvk[8];
#pragma unroll
    for (int g = 0; g < 8; g++) mvk[g] = ((gmask >> g) & 1u) ? sck[g] : key_f(0.0f);

    int se[8]; float ss[8];
    float prev = 0.f;
#pragma unroll
    for (int r = 0; r < 9; r++) {
        uint32_t bk = 0u; int bg = 0;
#pragma unroll
        for (int g = 0; g < 8; g++) if (mvk[g] > bk) { bk = mvk[g]; bg = g; }
        uint32_t maxk = __reduce_max_sync(0xffffffffu, bk);
        uint32_t cande = (bk == maxk) ? (uint32_t)(bg * 32 + lid) : 0xffffffffu;
        uint32_t be = __reduce_min_sync(0xffffffffu, cande);

        float v = 0.f;
        int og = (int)(be >> 5);
        if (lid == (int)(be & 31)) {
#pragma unroll
            for (int g = 0; g < 8; g++) if (g == og) v = sg[g];
        }
        float bs = __shfl_sync(0xffffffffu, v, (int)(be & 31));

        float maxv = unkey_f(maxk);
        if (r < 8) { se[r] = (int)be; ss[r] = bs; }
        if (r >= 1) fl = fl || (prev - maxv < TAU);
        prev = maxv;

        if (lid == (int)(be & 31)) {
#pragma unroll
            for (int g = 0; g < 8; g++) if (g == og) mvk[g] = 0u;
        }
    }

    if (lid == 0) {
        float sum = 0.f;
#pragma unroll
        for (int r = 0; r < 8; r++) sum += ss[r];
        float k = 2.5f / (sum + 1e-20f);
#pragma unroll
        for (int r = 0; r < 8; r++) out[(size_t)t * 8 + r] = (float)se[r];
        if (write_w) {
#pragma unroll
            for (int r = 0; r < 8; r++) out[(size_t)TOK * 8 + t * 8 + r] = ss[r] * k;
        }
        if (!CLEANUP && fl) {
            int p = atomicAdd(&g_flag_cnt, 1);
            if (p < MAXFLAG) g_flag_tok[p] = t;
        }
    }
}

__global__ void __launch_bounds__(256)
router_kernel(const float* __restrict__ bias, float* __restrict__ out, int write_w) {
    const int wid = threadIdx.x >> 5, lid = threadIdx.x & 31;
    const int t = blockIdx.x * 8 + wid;
    route_token<false>(g_logits + (size_t)t * NEXP, bias, out, t, lid, write_w);
}

// ---------------- exact cleanup: compensated fp32 dot for flagged tokens ----------------
__device__ __forceinline__ void kacc(float& s, float& c, float a, float b) {
    float p = a * b;
    float e = fmaf(a, b, -p);       // exact product residue
    float tt = s + p;               // 2Sum
    float bb = tt - s;
    float err = (s - (tt - bb)) + (p - bb);
    s = tt;
    c += err + e;
}
__device__ __forceinline__ void kmerge(float& s, float& c, float s2, float c2) {
    float tt = s + s2;
    float bb = tt - s;
    float err = (s - (tt - bb)) + (s2 - bb);
    s = tt;
    c = c + c2 + err;
}

__global__ void __launch_bounds__(256)
fix_logits_kernel(const float* __restrict__ X, const float* __restrict__ W) {
    int cnt = g_flag_cnt; if (cnt > MAXFLAG) cnt = MAXFLAG;
    const int ti = blockIdx.x >> 5;
    if (ti >= cnt) return;
    const int t = g_flag_tok[ti];
    const int sub = blockIdx.x & 31;
    const int wid = threadIdx.x >> 5, lid = threadIdx.x & 31;
    const int e = sub * 8 + wid;     // one expert per warp

    const float* xr = X + (size_t)t * HID;
    const float* wr = W + (size_t)e * HID;
    float s0 = 0.f, c0 = 0.f, s1 = 0.f, c1 = 0.f;
    float s2 = 0.f, c2 = 0.f, s3 = 0.f, c3 = 0.f;
#pragma unroll 4
    for (int it = 0; it < HID / 256; it++) {
        const float* xp = xr + it * 256 + lid * 4;
        const float* wp = wr + it * 256 + lid * 4;
        float4 xv0 = *reinterpret_cast<const float4*>(xp);
        float4 wv0 = *reinterpret_cast<const float4*>(wp);
        float4 xv1 = *reinterpret_cast<const float4*>(xp + 128);
        float4 wv1 = *reinterpret_cast<const float4*>(wp + 128);
        kacc(s0, c0, xv0.x, wv0.x);
        kacc(s1, c1, xv0.y, wv0.y);
        kacc(s2, c2, xv0.z, wv0.z);
        kacc(s3, c3, xv0.w, wv0.w);
        kacc(s0, c0, xv1.x, wv1.x);
        kacc(s1, c1, xv1.y, wv1.y);
        kacc(s2, c2, xv1.z, wv1.z);
        kacc(s3, c3, xv1.w, wv1.w);
    }
    kmerge(s0, c0, s1, c1);
    kmerge(s2, c2, s3, c3);
    kmerge(s0, c0, s2, c2);

#pragma unroll
    for (int off = 16; off > 0; off >>= 1) {
        float sx = __shfl_xor_sync(0xffffffffu, s0, off);
        float cx = __shfl_xor_sync(0xffffffffu, c0, off);
        kmerge(s0, c0, sx, cx);
    }
    if (lid == 0) g_fix_logit[(size_t)ti * NEXP + e] = s0 + c0;
}

__global__ void __launch_bounds__(256)
fix_select_kernel(const float* __restrict__ bias, float* __restrict__ out, int write_w) {
    int cnt = g_flag_cnt; if (cnt > MAXFLAG) cnt = MAXFLAG;
    const int wid = threadIdx.x >> 5, lid = threadIdx.x & 31;
    const int ti = blockIdx.x * 8 + wid;
    if (ti >= cnt) return;
    const int t = g_flag_tok[ti];
    route_token<true>(g_fix_logit + (size_t)ti * NEXP, bias, out, t, lid, write_w);
}

extern "C" void kernel_launch(void* const* d_in, const int* in_sizes, int n_in,
                              void* d_out, int out_size) {
    const float* x = (const float*)d_in[0];
    const float* w = (const float*)d_in[1];
    const float* b = (const float*)d_in[2];
    float* out = (float*)d_out;

    int write_w = (out_size >= TOK * 16) ? 1 : 0;

    cudaFuncSetAttribute(gemm_kernel, cudaFuncAttributeMaxDynamicSharedMemorySize, SMEM_TOTAL);
    gemm_kernel<<<dim3(NEXP / BN, TOK / BM, 1), 256, SMEM_TOTAL>>>(x, w);

    router_kernel<<<TOK / 8, 256>>>(b, out, write_w);
    fix_logits_kernel<<<32 * MAXFLAG, 256>>>(x, w);
    fix_select_kernel<<<MAXFLAG / 8, 256>>>(b, out, write_w);
}

// round 16
// speedup vs baseline: 1.1880x; 1.1880x over previous
#include <cuda_runtime.h>
#include <cuda_fp16.h>
#include <cstdint>
#include <math.h>

static constexpr int TOK  = 8192;
static constexpr int HID  = 7168;
static constexpr int NEXP = 256;
static constexpr int BM = 128, BN = 128, BK = 32;
static constexpr int KCH = HID / BK;                // 224
static constexpr int ARR_B   = 128 * 40 * 2;        // 10240 bytes per tile array
static constexpr int STAGE_B = 4 * ARR_B;           // Ah, Al, Bh, Bl
static constexpr int SMEM_TOTAL = 2 * STAGE_B;      // 81920 bytes
static constexpr int MAXFLAG = 256;
static constexpr float WSCALE = 4096.0f;            // keep wl out of fp16 subnormals
static constexpr float TAU   = 3e-6f;               // expert-margin flag threshold (score space)
static constexpr float TAU_G = 6e-6f;               // group-margin flag threshold

__device__ float g_logits[(size_t)TOK * NEXP];
__device__ int   g_flag_cnt;
__device__ int   g_flag_tok[MAXFLAG];
__device__ float g_fix_logit[(size_t)MAXFLAG * NEXP];

// ---------------- helpers ----------------
__device__ __forceinline__ uint32_t smem_u32(const void* p) {
    uint32_t a;
    asm("{ .reg .u64 t; cvta.to.shared.u64 t, %1; cvt.u32.u64 %0, t; }" : "=r"(a) : "l"(p));
    return a;
}
__device__ __forceinline__ void ldsm4(uint32_t* r, uint32_t addr) {
    asm volatile("ldmatrix.sync.aligned.m8n8.x4.shared.b16 {%0,%1,%2,%3}, [%4];"
                 : "=r"(r[0]), "=r"(r[1]), "=r"(r[2]), "=r"(r[3]) : "r"(addr));
}
__device__ __forceinline__ void ldsm2(uint32_t* r, uint32_t addr) {
    asm volatile("ldmatrix.sync.aligned.m8n8.x2.shared.b16 {%0,%1}, [%2];"
                 : "=r"(r[0]), "=r"(r[1]) : "r"(addr));
}
__device__ __forceinline__ void mma16816(float* c, const uint32_t* a, const uint32_t* b) {
    asm volatile("mma.sync.aligned.m16n8k16.row.col.f32.f16.f16.f32 "
                 "{%0,%1,%2,%3}, {%4,%5,%6,%7}, {%8,%9}, {%0,%1,%2,%3};"
                 : "+f"(c[0]), "+f"(c[1]), "+f"(c[2]), "+f"(c[3])
                 : "r"(a[0]), "r"(a[1]), "r"(a[2]), "r"(a[3]), "r"(b[0]), "r"(b[1]));
}
__device__ __forceinline__ uint32_t pack2(half a, half b) {
    __half2 h = __halves2half2(a, b);
    return *reinterpret_cast<uint32_t*>(&h);
}
// split (v*scale) -> hi(4 halves) + lo(4 halves)
__device__ __forceinline__ void split_store(float4 v, float scale, half* ph, half* pl) {
    float vx = v.x * scale, vy = v.y * scale, vz = v.z * scale, vw = v.w * scale;
    half hx = __float2half_rn(vx), hy = __float2half_rn(vy);
    half hz = __float2half_rn(vz), hw = __float2half_rn(vw);
    half lx = __float2half_rn(vx - __half2float(hx));
    half ly = __float2half_rn(vy - __half2float(hy));
    half lz = __float2half_rn(vz - __half2float(hz));
    half lw = __float2half_rn(vw - __half2float(hw));
    uint2 H, L;
    H.x = pack2(hx, hy); H.y = pack2(hz, hw);
    L.x = pack2(lx, ly); L.y = pack2(lz, lw);
    *reinterpret_cast<uint2*>(ph) = H;
    *reinterpret_cast<uint2*>(pl) = L;
}
// monotone u32 key for float compare (handles negatives)
__device__ __forceinline__ uint32_t key_f(float f) {
    uint32_t u = __float_as_uint(f);
    return (u & 0x80000000u) ? ~u : (u | 0x80000000u);
}
__device__ __forceinline__ float unkey_f(uint32_t k) {
    return __uint_as_float((k & 0x80000000u) ? (k ^ 0x80000000u) : ~k);
}

// ---------------- GEMM: logits = X @ W^T (fp16 2-term split, 3x mma.sync) ----------------
__global__ void __launch_bounds__(256, 1)
gemm_kernel(const float* __restrict__ X, const float* __restrict__ W) {
    extern __shared__ half sm[];
    const int tid = threadIdx.x;
    const int lid = tid & 31, wid = tid >> 5;
    const int warp_m = wid >> 2;          // 0..1
    const int warp_n = wid & 3;           // 0..3
    const int m0 = blockIdx.y * BM;
    const int n0 = blockIdx.x * BN;
    const uint32_t sb = smem_u32(sm);

    // reset flag counter for the router (runs strictly after this kernel)
    if (blockIdx.x == 0 && blockIdx.y == 0 && tid == 0) g_flag_cnt = 0;

    const float* Abase = X + (size_t)m0 * HID;
    const float* Bbase = W + (size_t)n0 * HID;

    const int aRow = warp_m * 64 + ((lid >> 3) & 1) * 8 + (lid & 7);
    const int aK   = (lid >> 4) * 8;
    const int bRow = warp_n * 32 + (lid & 7);
    const int bK   = ((lid >> 3) & 1) * 8;

    float acc[4][4][4];
#pragma unroll
    for (int i = 0; i < 4; i++)
#pragma unroll
        for (int j = 0; j < 4; j++)
#pragma unroll
            for (int k = 0; k < 4; k++) acc[i][j][k] = 0.f;

    float4 stg[8];

    // prologue: chunk 0
#pragma unroll
    for (int i = 0; i < 4; i++) {
        int idx = tid + 256 * i;
        stg[i]     = *reinterpret_cast<const float4*>(Abase + (size_t)(idx >> 3) * HID + (idx & 7) * 4);
        stg[4 + i] = *reinterpret_cast<const float4*>(Bbase + (size_t)(idx >> 3) * HID + (idx & 7) * 4);
    }
    {
        char* s0 = reinterpret_cast<char*>(sm);
#pragma unroll
        for (int i = 0; i < 4; i++) {
            int idx = tid + 256 * i;
            int pos = (idx >> 3) * 80 + (idx & 7) * 8;
            split_store(stg[i], 1.0f,       reinterpret_cast<half*>(s0 + pos),
                                            reinterpret_cast<half*>(s0 + ARR_B + pos));
            split_store(stg[4 + i], WSCALE, reinterpret_cast<half*>(s0 + 2 * ARR_B + pos),
                                            reinterpret_cast<half*>(s0 + 3 * ARR_B + pos));
        }
    }
    __syncthreads();

    for (int c = 0; c < KCH; c++) {
        const int buf = c & 1;
        if (c + 1 < KCH) {
            const int k0 = (c + 1) * BK;
#pragma unroll
            for (int i = 0; i < 4; i++) {
                int idx = tid + 256 * i;
                stg[i]     = *reinterpret_cast<const float4*>(Abase + (size_t)(idx >> 3) * HID + k0 + (idx & 7) * 4);
                stg[4 + i] = *reinterpret_cast<const float4*>(Bbase + (size_t)(idx >> 3) * HID + k0 + (idx & 7) * 4);
            }
        }

        const uint32_t base = sb + buf * STAGE_B;
#pragma unroll
        for (int ks = 0; ks < 2; ks++) {
            uint32_t ah[4][4], al[4][4], bh[4][2], bl[4][2];
#pragma unroll
            for (int mt = 0; mt < 4; mt++) {
                uint32_t ra = base + (uint32_t)((aRow + mt * 16) * 80 + (aK + ks * 16) * 2);
                ldsm4(ah[mt], ra);
                ldsm4(al[mt], ra + ARR_B);
            }
#pragma unroll
            for (int nt = 0; nt < 4; nt++) {
                uint32_t rb = base + 2 * ARR_B + (uint32_t)((bRow + nt * 8) * 80 + (bK + ks * 16) * 2);
                ldsm2(bh[nt], rb);
                ldsm2(bl[nt], rb + ARR_B);
            }
#pragma unroll
            for (int mt = 0; mt < 4; mt++)
#pragma unroll
                for (int nt = 0; nt < 4; nt++) {
                    mma16816(acc[mt][nt], ah[mt], bh[nt]);
                    mma16816(acc[mt][nt], ah[mt], bl[nt]);
                    mma16816(acc[mt][nt], al[mt], bh[nt]);
                }
        }

        if (c + 1 < KCH) {
            char* sn = reinterpret_cast<char*>(sm) + (buf ^ 1) * STAGE_B;
#pragma unroll
            for (int i = 0; i < 4; i++) {
                int idx = tid + 256 * i;
                int pos = (idx >> 3) * 80 + (idx & 7) * 8;
                split_store(stg[i], 1.0f,       reinterpret_cast<half*>(sn + pos),
                                                reinterpret_cast<half*>(sn + ARR_B + pos));
                split_store(stg[4 + i], WSCALE, reinterpret_cast<half*>(sn + 2 * ARR_B + pos),
                                                reinterpret_cast<half*>(sn + 3 * ARR_B + pos));
            }
        }
        __syncthreads();
    }

    const float inv = 1.0f / WSCALE;
#pragma unroll
    for (int mt = 0; mt < 4; mt++) {
        int row = m0 + warp_m * 64 + mt * 16 + (lid >> 2);
#pragma unroll
        for (int nt = 0; nt < 4; nt++) {
            int col = n0 + warp_n * 32 + nt * 8 + (lid & 3) * 2;
            *reinterpret_cast<float2*>(g_logits + (size_t)row * NEXP + col) =
                make_float2(acc[mt][nt][0] * inv, acc[mt][nt][1] * inv);
            *reinterpret_cast<float2*>(g_logits + (size_t)(row + 8) * NEXP + col) =
                make_float2(acc[mt][nt][2] * inv, acc[mt][nt][3] * inv);
        }
    }
}

// ---------------- routing decision (one warp per token, REDUX-based) ----------------
template<bool CLEANUP>
__device__ __forceinline__ void route_token(const float* __restrict__ lrow,
                                            const float* __restrict__ bias,
                                            float* __restrict__ out,
                                            int t, int lid, int write_w) {
    float sg[8];
    uint32_t sck[8];          // monotone keys of sc = s + bias
#pragma unroll
    for (int g = 0; g < 8; g++) {
        int e = g * 32 + lid;
        float x = lrow[e];
        float s;
        if (CLEANUP) s = (float)(1.0 / (1.0 + exp(-(double)x)));
        else         s = 1.0f / (1.0f + expf(-x));
        sg[g] = s;
        sck[g] = key_f(s + bias[e]);
    }

    // per-group top-2 sum via redux
    float gs[8];
#pragma unroll
    for (int g = 0; g < 8; g++) {
        uint32_t k = sck[g];
        uint32_t m1 = __reduce_max_sync(0xffffffffu, k);
        unsigned bal = __ballot_sync(0xffffffffu, k == m1);
        int low = __ffs(bal) - 1;
        uint32_t kk = (lid == low) ? 0u : k;
        uint32_t m2 = __reduce_max_sync(0xffffffffu, kk);
        gs[g] = unkey_f(m1) + unkey_f(m2);
    }

    // top-4 groups (lane-local, identical on all lanes; ties -> lowest g)
    unsigned gmask = 0;
    bool fl = false;
    {
        float tmp[8];
#pragma unroll
        for (int g = 0; g < 8; g++) tmp[g] = gs[g];
        float g4 = 0.f, g5 = 0.f;
#pragma unroll
        for (int it = 0; it < 5; it++) {
            float best = -INFINITY; int bi = 0;
#pragma unroll
            for (int g = 0; g < 8; g++) if (tmp[g] > best) { best = tmp[g]; bi = g; }
            if (it < 4) gmask |= 1u << bi;
            if (it == 3) g4 = best;
            if (it == 4) g5 = best;
#pragma unroll
            for (int g = 0; g < 8; g++) if (g == bi) tmp[g] = -INFINITY;
        }
        fl = (g4 - g5 < TAU_G);
    }

    uint32_t mvk[8];
#pragma unroll
    for (int g = 0; g < 8; g++) mvk[g] = ((gmask >> g) & 1u) ? sck[g] : key_f(0.0f);

    int se[8]; float ss[8];
    float prev = 0.f;
#pragma unroll
    for (int r = 0; r < 9; r++) {
        uint32_t bk = 0u; int bg = 0;
#pragma unroll
        for (int g = 0; g < 8; g++) if (mvk[g] > bk) { bk = mvk[g]; bg = g; }
        uint32_t maxk = __reduce_max_sync(0xffffffffu, bk);
        uint32_t cande = (bk == maxk) ? (uint32_t)(bg * 32 + lid) : 0xffffffffu;
        uint32_t be = __reduce_min_sync(0xffffffffu, cande);

        float v = 0.f;
        int og = (int)(be >> 5);
        if (lid == (int)(be & 31)) {
#pragma unroll
            for (int g = 0; g < 8; g++) if (g == og) v = sg[g];
        }
        float bs = __shfl_sync(0xffffffffu, v, (int)(be & 31));

        float maxv = unkey_f(maxk);
        if (r < 8) { se[r] = (int)be; ss[r] = bs; }
        if (r >= 1) fl = fl || (prev - maxv < TAU);
        prev = maxv;

        if (lid == (int)(be & 31)) {
#pragma unroll
            for (int g = 0; g < 8; g++) if (g == og) mvk[g] = 0u;
        }
    }

    if (lid == 0) {
        float sum = 0.f;
#pragma unroll
        for (int r = 0; r < 8; r++) sum += ss[r];
        float k = 2.5f / (sum + 1e-20f);
#pragma unroll
        for (int r = 0; r < 8; r++) out[(size_t)t * 8 + r] = (float)se[r];
        if (write_w) {
#pragma unroll
            for (int r = 0; r < 8; r++) out[(size_t)TOK * 8 + t * 8 + r] = ss[r] * k;
        }
        if (!CLEANUP && fl) {
            int p = atomicAdd(&g_flag_cnt, 1);
            if (p < MAXFLAG) g_flag_tok[p] = t;
        }
    }
}

__global__ void __launch_bounds__(256)
router_kernel(const float* __restrict__ bias, float* __restrict__ out, int write_w) {
    const int wid = threadIdx.x >> 5, lid = threadIdx.x & 31;
    const int t = blockIdx.x * 8 + wid;
    route_token<false>(g_logits + (size_t)t * NEXP, bias, out, t, lid, write_w);
}

// ---------------- exact cleanup: compensated fp32 dot for flagged tokens ----------------
__device__ __forceinline__ void kacc(float& s, float& c, float a, float b) {
    float p = a * b;
    float e = fmaf(a, b, -p);       // exact product residue
    float tt = s + p;               // 2Sum
    float bb = tt - s;
    float err = (s - (tt - bb)) + (p - bb);
    s = tt;
    c += err + e;
}
__device__ __forceinline__ void kmerge(float& s, float& c, float s2, float c2) {
    float tt = s + s2;
    float bb = tt - s;
    float err = (s - (tt - bb)) + (s2 - bb);
    s = tt;
    c = c + c2 + err;
}

// X row cached in SMEM once per block (8 warps share it) — removes the 8x
// redundant L2 re-read of the token's X row.
__global__ void __launch_bounds__(256)
fix_logits_kernel(const float* __restrict__ X, const float* __restrict__ W) {
    __shared__ float sx[HID];
    int cnt = g_flag_cnt; if (cnt > MAXFLAG) cnt = MAXFLAG;
    const int ti = blockIdx.x >> 5;
    if (ti >= cnt) return;
    const int t = g_flag_tok[ti];
    const int sub = blockIdx.x & 31;
    const int tid = threadIdx.x;
    const int wid = tid >> 5, lid = tid & 31;
    const int e = sub * 8 + wid;     // one expert per warp

    // stage X row into smem (7 float4 per thread)
    {
        const float4* xs = reinterpret_cast<const float4*>(X + (size_t)t * HID);
        float4* xd = reinterpret_cast<float4*>(sx);
#pragma unroll
        for (int i = 0; i < 7; i++) xd[tid + i * 256] = xs[tid + i * 256];
    }
    __syncthreads();

    const float* wr = W + (size_t)e * HID;
    float s0 = 0.f, c0 = 0.f, s1 = 0.f, c1 = 0.f;
    float s2 = 0.f, c2 = 0.f, s3 = 0.f, c3 = 0.f;
#pragma unroll 4
    for (int it = 0; it < HID / 256; it++) {
        const float* xp = sx + it * 256 + lid * 4;
        const float* wp = wr + it * 256 + lid * 4;
        float4 xv0 = *reinterpret_cast<const float4*>(xp);
        float4 wv0 = *reinterpret_cast<const float4*>(wp);
        float4 xv1 = *reinterpret_cast<const float4*>(xp + 128);
        float4 wv1 = *reinterpret_cast<const float4*>(wp + 128);
        kacc(s0, c0, xv0.x, wv0.x);
        kacc(s1, c1, xv0.y, wv0.y);
        kacc(s2, c2, xv0.z, wv0.z);
        kacc(s3, c3, xv0.w, wv0.w);
        kacc(s0, c0, xv1.x, wv1.x);
        kacc(s1, c1, xv1.y, wv1.y);
        kacc(s2, c2, xv1.z, wv1.z);
        kacc(s3, c3, xv1.w, wv1.w);
    }
    kmerge(s0, c0, s1, c1);
    kmerge(s2, c2, s3, c3);
    kmerge(s0, c0, s2, c2);

#pragma unroll
    for (int off = 16; off > 0; off >>= 1) {
        float sx2 = __shfl_xor_sync(0xffffffffu, s0, off);
        float cx2 = __shfl_xor_sync(0xffffffffu, c0, off);
        kmerge(s0, c0, sx2, cx2);
    }
    if (lid == 0) g_fix_logit[(size_t)ti * NEXP + e] = s0 + c0;
}

__global__ void __launch_bounds__(32)
fix_select_kernel(const float* __restrict__ bias, float* __restrict__ out, int write_w) {
    int cnt = g_flag_cnt; if (cnt > MAXFLAG) cnt = MAXFLAG;
    const int ti = blockIdx.x;
    if (ti >= cnt) return;
    const int t = g_flag_tok[ti];
    route_token<true>(g_fix_logit + (size_t)ti * NEXP, bias, out, t, threadIdx.x, write_w);
}

extern "C" void kernel_launch(void* const* d_in, const int* in_sizes, int n_in,
                              void* d_out, int out_size) {
    const float* x = (const float*)d_in[0];
    const float* w = (const float*)d_in[1];
    const float* b = (const float*)d_in[2];
    float* out = (float*)d_out;

    int write_w = (out_size >= TOK * 16) ? 1 : 0;

    cudaFuncSetAttribute(gemm_kernel, cudaFuncAttributeMaxDynamicSharedMemorySize, SMEM_TOTAL);
    gemm_kernel<<<dim3(NEXP / BN, TOK / BM, 1), 256, SMEM_TOTAL>>>(x, w);

    router_kernel<<<TOK / 8, 256>>>(b, out, write_w);
    fix_logits_kernel<<<32 * MAXFLAG, 256>>>(x, w);
    fix_select_kernel<<<MAXFLAG, 32>>>(b, out, write_w);
}

// round 17
// speedup vs baseline: 1.2256x; 1.0317x over previous
#include <cuda_runtime.h>
#include <cuda_fp16.h>
#include <cstdint>
#include <math.h>

static constexpr int TOK  = 8192;
static constexpr int HID  = 7168;
static constexpr int NEXP = 256;
static constexpr int BM = 128, BN = 128, BK = 32;
static constexpr int KCH = HID / BK;                // 224
static constexpr int ARR_B   = 128 * 40 * 2;        // 10240 bytes per tile array
static constexpr int STAGE_B = 4 * ARR_B;           // Ah, Al, Bh, Bl
static constexpr int SMEM_TOTAL = 2 * STAGE_B;      // 81920 bytes
static constexpr int MAXFLAG = 256;
static constexpr float WSCALE = 4096.0f;            // keep wl out of fp16 subnormals
static constexpr float TAU   = 3e-6f;               // expert-margin flag threshold (score space)
static constexpr float TAU_G = 6e-6f;               // group-margin flag threshold

__device__ float g_logits[(size_t)TOK * NEXP];
__device__ int   g_flag_cnt;
__device__ int   g_flag_tok[MAXFLAG];
__device__ float g_fix_logit[(size_t)MAXFLAG * NEXP];
__device__ int   g_fix_arrive[MAXFLAG];             // zero-init, self-cleaning

// ---------------- helpers ----------------
__device__ __forceinline__ uint32_t smem_u32(const void* p) {
    uint32_t a;
    asm("{ .reg .u64 t; cvta.to.shared.u64 t, %1; cvt.u32.u64 %0, t; }" : "=r"(a) : "l"(p));
    return a;
}
__device__ __forceinline__ void ldsm4(uint32_t* r, uint32_t addr) {
    asm volatile("ldmatrix.sync.aligned.m8n8.x4.shared.b16 {%0,%1,%2,%3}, [%4];"
                 : "=r"(r[0]), "=r"(r[1]), "=r"(r[2]), "=r"(r[3]) : "r"(addr));
}
__device__ __forceinline__ void ldsm2(uint32_t* r, uint32_t addr) {
    asm volatile("ldmatrix.sync.aligned.m8n8.x2.shared.b16 {%0,%1}, [%2];"
                 : "=r"(r[0]), "=r"(r[1]) : "r"(addr));
}
__device__ __forceinline__ void mma16816(float* c, const uint32_t* a, const uint32_t* b) {
    asm volatile("mma.sync.aligned.m16n8k16.row.col.f32.f16.f16.f32 "
                 "{%0,%1,%2,%3}, {%4,%5,%6,%7}, {%8,%9}, {%0,%1,%2,%3};"
                 : "+f"(c[0]), "+f"(c[1]), "+f"(c[2]), "+f"(c[3])
                 : "r"(a[0]), "r"(a[1]), "r"(a[2]), "r"(a[3]), "r"(b[0]), "r"(b[1]));
}
__device__ __forceinline__ uint32_t pack2(half a, half b) {
    __half2 h = __halves2half2(a, b);
    return *reinterpret_cast<uint32_t*>(&h);
}
// split (v*scale) -> hi(4 halves) + lo(4 halves)
__device__ __forceinline__ void split_store(float4 v, float scale, half* ph, half* pl) {
    float vx = v.x * scale, vy = v.y * scale, vz = v.z * scale, vw = v.w * scale;
    half hx = __float2half_rn(vx), hy = __float2half_rn(vy);
    half hz = __float2half_rn(vz), hw = __float2half_rn(vw);
    half lx = __float2half_rn(vx - __half2float(hx));
    half ly = __float2half_rn(vy - __half2float(hy));
    half lz = __float2half_rn(vz - __half2float(hz));
    half lw = __float2half_rn(vw - __half2float(hw));
    uint2 H, L;
    H.x = pack2(hx, hy); H.y = pack2(hz, hw);
    L.x = pack2(lx, ly); L.y = pack2(lz, lw);
    *reinterpret_cast<uint2*>(ph) = H;
    *reinterpret_cast<uint2*>(pl) = L;
}
// monotone u32 key for float compare (handles negatives)
__device__ __forceinline__ uint32_t key_f(float f) {
    uint32_t u = __float_as_uint(f);
    return (u & 0x80000000u) ? ~u : (u | 0x80000000u);
}
__device__ __forceinline__ float unkey_f(uint32_t k) {
    return __uint_as_float((k & 0x80000000u) ? (k ^ 0x80000000u) : ~k);
}

// ---------------- GEMM: logits = X @ W^T (fp16 2-term split, 3x mma.sync) ----------------
__global__ void __launch_bounds__(256, 1)
gemm_kernel(const float* __restrict__ X, const float* __restrict__ W) {
    extern __shared__ half sm[];
    const int tid = threadIdx.x;
    const int lid = tid & 31, wid = tid >> 5;
    const int warp_m = wid >> 2;          // 0..1
    const int warp_n = wid & 3;           // 0..3
    const int m0 = blockIdx.y * BM;
    const int n0 = blockIdx.x * BN;
    const uint32_t sb = smem_u32(sm);

    // reset flag counter for the router (runs strictly after this kernel)
    if (blockIdx.x == 0 && blockIdx.y == 0 && tid == 0) g_flag_cnt = 0;

    const float* Abase = X + (size_t)m0 * HID;
    const float* Bbase = W + (size_t)n0 * HID;

    const int aRow = warp_m * 64 + ((lid >> 3) & 1) * 8 + (lid & 7);
    const int aK   = (lid >> 4) * 8;
    const int bRow = warp_n * 32 + (lid & 7);
    const int bK   = ((lid >> 3) & 1) * 8;

    float acc[4][4][4];
#pragma unroll
    for (int i = 0; i < 4; i++)
#pragma unroll
        for (int j = 0; j < 4; j++)
#pragma unroll
            for (int k = 0; k < 4; k++) acc[i][j][k] = 0.f;

    float4 stg[8];

    // prologue: chunk 0
#pragma unroll
    for (int i = 0; i < 4; i++) {
        int idx = tid + 256 * i;
        stg[i]     = *reinterpret_cast<const float4*>(Abase + (size_t)(idx >> 3) * HID + (idx & 7) * 4);
        stg[4 + i] = *reinterpret_cast<const float4*>(Bbase + (size_t)(idx >> 3) * HID + (idx & 7) * 4);
    }
    {
        char* s0 = reinterpret_cast<char*>(sm);
#pragma unroll
        for (int i = 0; i < 4; i++) {
            int idx = tid + 256 * i;
            int pos = (idx >> 3) * 80 + (idx & 7) * 8;
            split_store(stg[i], 1.0f,       reinterpret_cast<half*>(s0 + pos),
                                            reinterpret_cast<half*>(s0 + ARR_B + pos));
            split_store(stg[4 + i], WSCALE, reinterpret_cast<half*>(s0 + 2 * ARR_B + pos),
                                            reinterpret_cast<half*>(s0 + 3 * ARR_B + pos));
        }
    }
    __syncthreads();

    for (int c = 0; c < KCH; c++) {
        const int buf = c & 1;
        if (c + 1 < KCH) {
            const int k0 = (c + 1) * BK;
#pragma unroll
            for (int i = 0; i < 4; i++) {
                int idx = tid + 256 * i;
                stg[i]     = *reinterpret_cast<const float4*>(Abase + (size_t)(idx >> 3) * HID + k0 + (idx & 7) * 4);
                stg[4 + i] = *reinterpret_cast<const float4*>(Bbase + (size_t)(idx >> 3) * HID + k0 + (idx & 7) * 4);
            }
        }

        const uint32_t base = sb + buf * STAGE_B;
#pragma unroll
        for (int ks = 0; ks < 2; ks++) {
            uint32_t ah[4][4], al[4][4], bh[4][2], bl[4][2];
#pragma unroll
            for (int mt = 0; mt < 4; mt++) {
                uint32_t ra = base + (uint32_t)((aRow + mt * 16) * 80 + (aK + ks * 16) * 2);
                ldsm4(ah[mt], ra);
                ldsm4(al[mt], ra + ARR_B);
            }
#pragma unroll
            for (int nt = 0; nt < 4; nt++) {
                uint32_t rb = base + 2 * ARR_B + (uint32_t)((bRow + nt * 8) * 80 + (bK + ks * 16) * 2);
                ldsm2(bh[nt], rb);
                ldsm2(bl[nt], rb + ARR_B);
            }
#pragma unroll
            for (int mt = 0; mt < 4; mt++)
#pragma unroll
                for (int nt = 0; nt < 4; nt++) {
                    mma16816(acc[mt][nt], ah[mt], bh[nt]);
                    mma16816(acc[mt][nt], ah[mt], bl[nt]);
                    mma16816(acc[mt][nt], al[mt], bh[nt]);
                }
        }

        if (c + 1 < KCH) {
            char* sn = reinterpret_cast<char*>(sm) + (buf ^ 1) * STAGE_B;
#pragma unroll
            for (int i = 0; i < 4; i++) {
                int idx = tid + 256 * i;
                int pos = (idx >> 3) * 80 + (idx & 7) * 8;
                split_store(stg[i], 1.0f,       reinterpret_cast<half*>(sn + pos),
                                                reinterpret_cast<half*>(sn + ARR_B + pos));
                split_store(stg[4 + i], WSCALE, reinterpret_cast<half*>(sn + 2 * ARR_B + pos),
                                                reinterpret_cast<half*>(sn + 3 * ARR_B + pos));
            }
        }
        __syncthreads();
    }

    const float inv = 1.0f / WSCALE;
#pragma unroll
    for (int mt = 0; mt < 4; mt++) {
        int row = m0 + warp_m * 64 + mt * 16 + (lid >> 2);
#pragma unroll
        for (int nt = 0; nt < 4; nt++) {
            int col = n0 + warp_n * 32 + nt * 8 + (lid & 3) * 2;
            *reinterpret_cast<float2*>(g_logits + (size_t)row * NEXP + col) =
                make_float2(acc[mt][nt][0] * inv, acc[mt][nt][1] * inv);
            *reinterpret_cast<float2*>(g_logits + (size_t)(row + 8) * NEXP + col) =
                make_float2(acc[mt][nt][2] * inv, acc[mt][nt][3] * inv);
        }
    }
}

// ---------------- routing decision (one warp per token, REDUX-based) ----------------
template<bool CLEANUP>
__device__ __forceinline__ void route_token(const float* __restrict__ lrow,
                                            const float* __restrict__ bias,
                                            float* __restrict__ out,
                                            int t, int lid, int write_w) {
    float sg[8];
    uint32_t sck[8];          // monotone keys of sc = s + bias
#pragma unroll
    for (int g = 0; g < 8; g++) {
        int e = g * 32 + lid;
        float x = lrow[e];
        float s;
        if (CLEANUP) s = (float)(1.0 / (1.0 + exp(-(double)x)));
        else         s = 1.0f / (1.0f + expf(-x));
        sg[g] = s;
        sck[g] = key_f(s + bias[e]);
    }

    // per-group top-2 sum via redux
    float gs[8];
#pragma unroll
    for (int g = 0; g < 8; g++) {
        uint32_t k = sck[g];
        uint32_t m1 = __reduce_max_sync(0xffffffffu, k);
        unsigned bal = __ballot_sync(0xffffffffu, k == m1);
        int low = __ffs(bal) - 1;
        uint32_t kk = (lid == low) ? 0u : k;
        uint32_t m2 = __reduce_max_sync(0xffffffffu, kk);
        gs[g] = unkey_f(m1) + unkey_f(m2);
    }

    // top-4 groups (lane-local, identical on all lanes; ties -> lowest g)
    unsigned gmask = 0;
    bool fl = false;
    {
        float tmp[8];
#pragma unroll
        for (int g = 0; g < 8; g++) tmp[g] = gs[g];
        float g4 = 0.f, g5 = 0.f;
#pragma unroll
        for (int it = 0; it < 5; it++) {
            float best = -INFINITY; int bi = 0;
#pragma unroll
            for (int g = 0; g < 8; g++) if (tmp[g] > best) { best = tmp[g]; bi = g; }
            if (it < 4) gmask |= 1u << bi;
            if (it == 3) g4 = best;
            if (it == 4) g5 = best;
#pragma unroll
            for (int g = 0; g < 8; g++) if (g == bi) tmp[g] = -INFINITY;
        }
        fl = (g4 - g5 < TAU_G);
    }

    uint32_t mvk[8];
#pragma unroll
    for (int g = 0; g < 8; g++) mvk[g] = ((gmask >> g) & 1u) ? sck[g] : key_f(0.0f);

    int se[8]; float ss[8];
    float prev = 0.f;
#pragma unroll
    for (int r = 0; r < 9; r++) {
        uint32_t bk = 0u; int bg = 0;
#pragma unroll
        for (int g = 0; g < 8; g++) if (mvk[g] > bk) { bk = mvk[g]; bg = g; }
        uint32_t maxk = __reduce_max_sync(0xffffffffu, bk);
        uint32_t cande = (bk == maxk) ? (uint32_t)(bg * 32 + lid) : 0xffffffffu;
        uint32_t be = __reduce_min_sync(0xffffffffu, cande);

        float v = 0.f;
        int og = (int)(be >> 5);
        if (lid == (int)(be & 31)) {
#pragma unroll
            for (int g = 0; g < 8; g++) if (g == og) v = sg[g];
        }
        float bs = __shfl_sync(0xffffffffu, v, (int)(be & 31));

        float maxv = unkey_f(maxk);
        if (r < 8) { se[r] = (int)be; ss[r] = bs; }
        if (r >= 1) fl = fl || (prev - maxv < TAU);
        prev = maxv;

        if (lid == (int)(be & 31)) {
#pragma unroll
            for (int g = 0; g < 8; g++) if (g == og) mvk[g] = 0u;
        }
    }

    if (lid == 0) {
        float sum = 0.f;
#pragma unroll
        for (int r = 0; r < 8; r++) sum += ss[r];
        float k = 2.5f / (sum + 1e-20f);
#pragma unroll
        for (int r = 0; r < 8; r++) out[(size_t)t * 8 + r] = (float)se[r];
        if (write_w) {
#pragma unroll
            for (int r = 0; r < 8; r++) out[(size_t)TOK * 8 + t * 8 + r] = ss[r] * k;
        }
        if (!CLEANUP && fl) {
            int p = atomicAdd(&g_flag_cnt, 1);
            if (p < MAXFLAG) g_flag_tok[p] = t;
        }
    }
}

__global__ void __launch_bounds__(256)
router_kernel(const float* __restrict__ bias, float* __restrict__ out, int write_w) {
    const int wid = threadIdx.x >> 5, lid = threadIdx.x & 31;
    const int t = blockIdx.x * 8 + wid;
    route_token<false>(g_logits + (size_t)t * NEXP, bias, out, t, lid, write_w);
}

// ---------------- exact cleanup: compensated fp32 dot for flagged tokens ----------------
__device__ __forceinline__ void kacc(float& s, float& c, float a, float b) {
    float p = a * b;
    float e = fmaf(a, b, -p);       // exact product residue
    float tt = s + p;               // 2Sum
    float bb = tt - s;
    float err = (s - (tt - bb)) + (p - bb);
    s = tt;
    c += err + e;
}
__device__ __forceinline__ void kmerge(float& s, float& c, float s2, float c2) {
    float tt = s + s2;
    float bb = tt - s;
    float err = (s - (tt - bb)) + (s2 - bb);
    s = tt;
    c = c + c2 + err;
}

// X row cached in SMEM once per block (8 warps share it). The 32nd-arriving
// block of each flagged token also routes it (fused fix_select).
__global__ void __launch_bounds__(256)
fix_logits_kernel(const float* __restrict__ X, const float* __restrict__ W,
                  const float* __restrict__ bias, float* __restrict__ out, int write_w) {
    __shared__ float sx[HID];
    __shared__ int s_turn;
    int cnt = g_flag_cnt; if (cnt > MAXFLAG) cnt = MAXFLAG;
    const int ti = blockIdx.x >> 5;
    if (ti >= cnt) return;
    const int t = g_flag_tok[ti];
    const int sub = blockIdx.x & 31;
    const int tid = threadIdx.x;
    const int wid = tid >> 5, lid = tid & 31;
    const int e = sub * 8 + wid;     // one expert per warp

    // stage X row into smem (7 float4 per thread)
    {
        const float4* xs = reinterpret_cast<const float4*>(X + (size_t)t * HID);
        float4* xd = reinterpret_cast<float4*>(sx);
#pragma unroll
        for (int i = 0; i < 7; i++) xd[tid + i * 256] = xs[tid + i * 256];
    }
    __syncthreads();

    const float* wr = W + (size_t)e * HID;
    float s0 = 0.f, c0 = 0.f, s1 = 0.f, c1 = 0.f;
    float s2 = 0.f, c2 = 0.f, s3 = 0.f, c3 = 0.f;
#pragma unroll 4
    for (int it = 0; it < HID / 256; it++) {
        const float* xp = sx + it * 256 + lid * 4;
        const float* wp = wr + it * 256 + lid * 4;
        float4 xv0 = *reinterpret_cast<const float4*>(xp);
        float4 wv0 = *reinterpret_cast<const float4*>(wp);
        float4 xv1 = *reinterpret_cast<const float4*>(xp + 128);
        float4 wv1 = *reinterpret_cast<const float4*>(wp + 128);
        kacc(s0, c0, xv0.x, wv0.x);
        kacc(s1, c1, xv0.y, wv0.y);
        kacc(s2, c2, xv0.z, wv0.z);
        kacc(s3, c3, xv0.w, wv0.w);
        kacc(s0, c0, xv1.x, wv1.x);
        kacc(s1, c1, xv1.y, wv1.y);
        kacc(s2, c2, xv1.z, wv1.z);
        kacc(s3, c3, xv1.w, wv1.w);
    }
    kmerge(s0, c0, s1, c1);
    kmerge(s2, c2, s3, c3);
    kmerge(s0, c0, s2, c2);

#pragma unroll
    for (int off = 16; off > 0; off >>= 1) {
        float sx2 = __shfl_xor_sync(0xffffffffu, s0, off);
        float cx2 = __shfl_xor_sync(0xffffffffu, c0, off);
        kmerge(s0, c0, sx2, cx2);
    }
    if (lid == 0) g_fix_logit[(size_t)ti * NEXP + e] = s0 + c0;

    // ---- fused selection: 32nd-arriving block routes this token ----
    __syncthreads();                      // all 8 expert logits of this block written
    __threadfence();                      // publish before arrival
    if (tid == 0) s_turn = atomicAdd(&g_fix_arrive[ti], 1);
    __syncthreads();
    if (s_turn == 31) {
        __threadfence();                  // acquire: see all 32 blocks' logits
        if (wid == 0)
            route_token<true>(g_fix_logit + (size_t)ti * NEXP, bias, out, t, lid, write_w);
        __syncthreads();
        if (tid == 0) g_fix_arrive[ti] = 0;   // self-clean for graph replay
    }
}

extern "C" void kernel_launch(void* const* d_in, const int* in_sizes, int n_in,
                              void* d_out, int out_size) {
    const float* x = (const float*)d_in[0];
    const float* w = (const float*)d_in[1];
    const float* b = (const float*)d_in[2];
    float* out = (float*)d_out;

    int write_w = (out_size >= TOK * 16) ? 1 : 0;

    cudaFuncSetAttribute(gemm_kernel, cudaFuncAttributeMaxDynamicSharedMemorySize, SMEM_TOTAL);
    gemm_kernel<<<dim3(NEXP / BN, TOK / BM, 1), 256, SMEM_TOTAL>>>(x, w);

    router_kernel<<<TOK / 8, 256>>>(b, out, write_w);
    fix_logits_kernel<<<32 * MAXFLAG, 256>>>(x, w, b, out, write_w);
}